// round 2
// baseline (speedup 1.0000x reference)
#include <cuda_runtime.h>

// Scaled dot-product attention, B=4 H=16 S=2048 D=64, fp32.
// Flash-attention: per CTA one (head, 64-query tile); online softmax.
// 256 threads = 16x16; each thread owns a 4x4 tile of scores / output.

#define BM 64      // query rows per CTA
#define BN 64      // key rows per tile
#define DH 64      // head dim
#define TM 4
#define TN 4

__global__ __launch_bounds__(256) void attn_ffma_kernel(
    const float* __restrict__ Q,
    const float* __restrict__ K,
    const float* __restrict__ V,
    float* __restrict__ O,
    int S)
{
    // Qs[d][r]  (transposed)           : 64*64 floats
    // KPs = Ks[d][c] (transposed) then Ps[r][k] (natural), aliased
    // Vs[k][c]  (natural)
    __shared__ float Qs[DH * BM];
    __shared__ float KPs[DH * BN];
    __shared__ float Vs[BN * DH];

    const int tid = threadIdx.x;
    const int tx = tid & 15;        // score-column group
    const int ty = tid >> 4;        // score-row group
    const int head = blockIdx.y;    // 0..63 (b*H+h)
    const int qbase = blockIdx.x * BM;
    const size_t base = (size_t)head * S * DH;

    // ---- load Q tile, store transposed Qs[d][r] ----
    #pragma unroll
    for (int it = 0; it < 4; ++it) {
        int idx = tid + it * 256;           // 0..1023 float4 chunks
        int r = idx >> 4;                   // 0..63
        int d4 = (idx & 15) << 2;           // 0,4,..,60
        float4 v = *(const float4*)&Q[base + (size_t)(qbase + r) * DH + d4];
        Qs[(d4 + 0) * BM + r] = v.x;
        Qs[(d4 + 1) * BM + r] = v.y;
        Qs[(d4 + 2) * BM + r] = v.z;
        Qs[(d4 + 3) * BM + r] = v.w;
    }

    float m[TM], l[TM], acc[TM][TN];
    #pragma unroll
    for (int i = 0; i < TM; ++i) {
        m[i] = -1e30f;
        l[i] = 0.0f;
        #pragma unroll
        for (int j = 0; j < TN; ++j) acc[i][j] = 0.0f;
    }

    const int nkt = S / BN;
    for (int kt = 0; kt < nkt; ++kt) {
        const int kb = kt * BN;

        // protect Ps (in KPs) from previous iteration's GEMM2 readers
        __syncthreads();

        // ---- load K tile transposed: KPs[d][c] ----
        #pragma unroll
        for (int it = 0; it < 4; ++it) {
            int idx = tid + it * 256;
            int c = idx >> 4;
            int d4 = (idx & 15) << 2;
            float4 v = *(const float4*)&K[base + (size_t)(kb + c) * DH + d4];
            KPs[(d4 + 0) * BN + c] = v.x;
            KPs[(d4 + 1) * BN + c] = v.y;
            KPs[(d4 + 2) * BN + c] = v.z;
            KPs[(d4 + 3) * BN + c] = v.w;
        }
        // ---- load V tile natural: Vs[k][c] ----
        #pragma unroll
        for (int it = 0; it < 4; ++it) {
            int idx = tid + it * 256;
            int k = idx >> 4;
            int d4 = (idx & 15) << 2;
            *(float4*)&Vs[k * DH + d4] =
                *(const float4*)&V[base + (size_t)(kb + k) * DH + d4];
        }
        __syncthreads();

        // ---- GEMM1: s = Q_tile @ K_tile^T ----
        float s[TM][TN];
        #pragma unroll
        for (int i = 0; i < TM; ++i)
            #pragma unroll
            for (int j = 0; j < TN; ++j) s[i][j] = 0.0f;

        #pragma unroll 4
        for (int d = 0; d < DH; ++d) {
            float4 a = *(const float4*)&Qs[d * BM + ty * TM];
            float4 b = *(const float4*)&KPs[d * BN + tx * TN];
            s[0][0] += a.x * b.x; s[0][1] += a.x * b.y; s[0][2] += a.x * b.z; s[0][3] += a.x * b.w;
            s[1][0] += a.y * b.x; s[1][1] += a.y * b.y; s[1][2] += a.y * b.z; s[1][3] += a.y * b.w;
            s[2][0] += a.z * b.x; s[2][1] += a.z * b.y; s[2][2] += a.z * b.z; s[2][3] += a.z * b.w;
            s[3][0] += a.w * b.x; s[3][1] += a.w * b.y; s[3][2] += a.w * b.z; s[3][3] += a.w * b.w;
        }

        // ---- online softmax update (scale = 1/sqrt(64) = 0.125) ----
        const float scale = 0.125f;
        #pragma unroll
        for (int i = 0; i < TM; ++i) {
            #pragma unroll
            for (int j = 0; j < TN; ++j) s[i][j] *= scale;

            float rmax = fmaxf(fmaxf(s[i][0], s[i][1]), fmaxf(s[i][2], s[i][3]));
            // reduce across the 16 threads owning this row (lanes differ in bits 0..3)
            #pragma unroll
            for (int off = 8; off >= 1; off >>= 1)
                rmax = fmaxf(rmax, __shfl_xor_sync(0xffffffffu, rmax, off));

            float mnew = fmaxf(m[i], rmax);
            float f = __expf(m[i] - mnew);      // underflows to 0 on first tile

            float rsum = 0.0f;
            #pragma unroll
            for (int j = 0; j < TN; ++j) {
                s[i][j] = __expf(s[i][j] - mnew);
                rsum += s[i][j];
            }
            #pragma unroll
            for (int off = 8; off >= 1; off >>= 1)
                rsum += __shfl_xor_sync(0xffffffffu, rsum, off);

            l[i] = l[i] * f + rsum;
            m[i] = mnew;
            #pragma unroll
            for (int j = 0; j < TN; ++j) acc[i][j] *= f;
        }

        // KPs no longer needed as K: write P into it (natural layout Ps[r][k])
        __syncthreads();
        #pragma unroll
        for (int i = 0; i < TM; ++i)
            #pragma unroll
            for (int j = 0; j < TN; ++j)
                KPs[(ty * TM + i) * BN + tx * TN + j] = s[i][j];
        __syncthreads();

        // ---- GEMM2: acc += P @ V_tile ----
        #pragma unroll 4
        for (int k = 0; k < BN; ++k) {
            float4 b = *(const float4*)&Vs[k * DH + tx * TN];
            float a0 = KPs[(ty * TM + 0) * BN + k];
            float a1 = KPs[(ty * TM + 1) * BN + k];
            float a2 = KPs[(ty * TM + 2) * BN + k];
            float a3 = KPs[(ty * TM + 3) * BN + k];
            acc[0][0] += a0 * b.x; acc[0][1] += a0 * b.y; acc[0][2] += a0 * b.z; acc[0][3] += a0 * b.w;
            acc[1][0] += a1 * b.x; acc[1][1] += a1 * b.y; acc[1][2] += a1 * b.z; acc[1][3] += a1 * b.w;
            acc[2][0] += a2 * b.x; acc[2][1] += a2 * b.y; acc[2][2] += a2 * b.z; acc[2][3] += a2 * b.w;
            acc[3][0] += a3 * b.x; acc[3][1] += a3 * b.y; acc[3][2] += a3 * b.z; acc[3][3] += a3 * b.w;
        }
    }

    // ---- epilogue: normalize and store ----
    #pragma unroll
    for (int i = 0; i < TM; ++i) {
        float inv = 1.0f / l[i];
        float4 o;
        o.x = acc[i][0] * inv;
        o.y = acc[i][1] * inv;
        o.z = acc[i][2] * inv;
        o.w = acc[i][3] * inv;
        *(float4*)&O[base + (size_t)(qbase + ty * TM + i) * DH + tx * TN] = o;
    }
}

extern "C" void kernel_launch(void* const* d_in, const int* in_sizes, int n_in,
                              void* d_out, int out_size)
{
    const float* Q = (const float*)d_in[0];
    const float* K = (const float*)d_in[1];
    const float* V = (const float*)d_in[2];
    float* O = (float*)d_out;

    // B=4, H=16, S=2048, D=64  (fixed by the problem)
    const int BH = 64;
    const int S = 2048;

    dim3 grid(S / BM, BH);
    attn_ffma_kernel<<<grid, 256>>>(Q, K, V, O, S);
}

// round 6
// speedup vs baseline: 1.2539x; 1.2539x over previous
#include <cuda_runtime.h>

// Scaled dot-product attention, B=4 H=16 S=2048 D=64, fp32.
// Flash-attention with packed f32x2 FMA (FFMA2) on sm_103a.
// CTA tile: 128 queries x 128 keys. 256 threads (16x16).
// Per thread: 8x8 score tile (4 row-pairs x 8 cols, packed u64),
//             8x4 output tile (4 row-pairs x 4 cols, packed u64).

#define BM 128
#define BN 128
#define DH 64
#define NT 256

#define QS_STRIDE 132   // floats per d-row (pad: keeps 16B align, reduces store conflicts)
#define KS_STRIDE 132
#define VS_STRIDE 68

#define QS_OFF 0
#define KS_OFF (DH * QS_STRIDE * 4)               /* 33792 */
#define PS_OFF KS_OFF                              /* alias K^T region */
#define VS_OFF (KS_OFF + BN * 64 * 8)              /* 33792 + 65536 = 99328 */
#define SMEM_BYTES (VS_OFF + BN * VS_STRIDE * 4)   /* 134144 */

typedef unsigned long long u64;

__device__ __forceinline__ u64 splat2(float x) {
    u64 r;
    asm("mov.b64 %0, {%1, %1};" : "=l"(r) : "r"(__float_as_uint(x)));
    return r;
}
__device__ __forceinline__ u64 pack2(float lo, float hi) {
    u64 r;
    asm("mov.b64 %0, {%1, %2};" : "=l"(r) : "r"(__float_as_uint(lo)), "r"(__float_as_uint(hi)));
    return r;
}
__device__ __forceinline__ void ffma2(u64& d, u64 a, u64 b) {
    asm("fma.rn.f32x2 %0, %1, %2, %0;" : "+l"(d) : "l"(a), "l"(b));
}
__device__ __forceinline__ void fmul2(u64& d, u64 a) {
    asm("mul.rn.f32x2 %0, %0, %1;" : "+l"(d) : "l"(a));
}
__device__ __forceinline__ float lo2(u64 u) { return __uint_as_float((unsigned)u); }
__device__ __forceinline__ float hi2(u64 u) { return __uint_as_float((unsigned)(u >> 32)); }
__device__ __forceinline__ float ex2f(float x) {
    float r; asm("ex2.approx.f32 %0, %1;" : "=f"(r) : "f"(x)); return r;
}

__global__ void __launch_bounds__(NT, 1) attn_f32x2_kernel(
    const float* __restrict__ Q,
    const float* __restrict__ K,
    const float* __restrict__ V,
    float* __restrict__ O,
    int S)
{
    extern __shared__ char smem[];
    float* Qs = (float*)(smem + QS_OFF);   // Q^T [d][row], pre-scaled
    float* Ks = (float*)(smem + KS_OFF);   // K^T [d][col]
    u64*   Ps = (u64*)(smem + PS_OFF);     // P row-pairs [k][64], rotated
    float* Vs = (float*)(smem + VS_OFF);   // V natural [k][d]

    const int tid = threadIdx.x;
    const int tx = tid & 15;       // score-column group / output-col group
    const int ty = tid >> 4;       // row group (8 rows)
    const size_t base = (size_t)blockIdx.y * ((size_t)S * DH);
    const int qbase = blockIdx.x * BM;

    // ---- load Q tile, pre-scaled by 1/sqrt(D)*log2(e), transposed ----
    const float SC = 0.125f * 1.4426950408889634f;
    #pragma unroll
    for (int it = 0; it < 8; ++it) {
        int idx = tid + it * NT;
        int row = idx >> 4;
        int d4 = (idx & 15) << 2;
        float4 v = *(const float4*)&Q[base + (size_t)(qbase + row) * DH + d4];
        Qs[(d4 + 0) * QS_STRIDE + row] = v.x * SC;
        Qs[(d4 + 1) * QS_STRIDE + row] = v.y * SC;
        Qs[(d4 + 2) * QS_STRIDE + row] = v.z * SC;
        Qs[(d4 + 3) * QS_STRIDE + row] = v.w * SC;
    }

    u64 acc[4][4];                 // output: 4 row-pairs x 4 cols (packed rows)
    float m[8], l[8];
    #pragma unroll
    for (int rp = 0; rp < 4; ++rp)
        #pragma unroll
        for (int j = 0; j < 4; ++j) acc[rp][j] = 0ull;
    #pragma unroll
    for (int r = 0; r < 8; ++r) { m[r] = -1e30f; l[r] = 0.0f; }

    const int nkt = S / BN;
    for (int kt = 0; kt < nkt; ++kt) {
        const int kb = kt * BN;
        __syncthreads();   // prev-iter Ps/Vs consumers done; Q^T ready (iter 0)

        // ---- load K tile transposed ----
        #pragma unroll
        for (int it = 0; it < 8; ++it) {
            int idx = tid + it * NT;
            int row = idx >> 4;
            int d4 = (idx & 15) << 2;
            float4 v = *(const float4*)&K[base + (size_t)(kb + row) * DH + d4];
            Ks[(d4 + 0) * KS_STRIDE + row] = v.x;
            Ks[(d4 + 1) * KS_STRIDE + row] = v.y;
            Ks[(d4 + 2) * KS_STRIDE + row] = v.z;
            Ks[(d4 + 3) * KS_STRIDE + row] = v.w;
        }
        // ---- load V tile natural ----
        #pragma unroll
        for (int it = 0; it < 8; ++it) {
            int idx = tid + it * NT;
            int row = idx >> 4;
            int d4 = (idx & 15) << 2;
            *(float4*)&Vs[row * VS_STRIDE + d4] =
                *(const float4*)&V[base + (size_t)(kb + row) * DH + d4];
        }
        __syncthreads();

        // ---- GEMM1: s = Q_tile @ K_tile^T (packed over row pairs) ----
        u64 s2[4][8];
        #pragma unroll
        for (int rp = 0; rp < 4; ++rp)
            #pragma unroll
            for (int j = 0; j < 8; ++j) s2[rp][j] = 0ull;

        const float* qp = Qs + ty * 8;
        const float* kp = Ks + tx * 8;
        #pragma unroll 2
        for (int d = 0; d < DH; ++d) {
            ulonglong2 A0 = *(const ulonglong2*)(qp + d * QS_STRIDE);
            ulonglong2 A1 = *(const ulonglong2*)(qp + d * QS_STRIDE + 4);
            float4 B0 = *(const float4*)(kp + d * KS_STRIDE);
            float4 B1 = *(const float4*)(kp + d * KS_STRIDE + 4);
            u64 b0 = splat2(B0.x), b1 = splat2(B0.y), b2 = splat2(B0.z), b3 = splat2(B0.w);
            u64 b4 = splat2(B1.x), b5 = splat2(B1.y), b6 = splat2(B1.z), b7 = splat2(B1.w);
            u64 a0 = A0.x, a1 = A0.y, a2 = A1.x, a3 = A1.y;
            ffma2(s2[0][0], a0, b0); ffma2(s2[0][1], a0, b1); ffma2(s2[0][2], a0, b2); ffma2(s2[0][3], a0, b3);
            ffma2(s2[0][4], a0, b4); ffma2(s2[0][5], a0, b5); ffma2(s2[0][6], a0, b6); ffma2(s2[0][7], a0, b7);
            ffma2(s2[1][0], a1, b0); ffma2(s2[1][1], a1, b1); ffma2(s2[1][2], a1, b2); ffma2(s2[1][3], a1, b3);
            ffma2(s2[1][4], a1, b4); ffma2(s2[1][5], a1, b5); ffma2(s2[1][6], a1, b6); ffma2(s2[1][7], a1, b7);
            ffma2(s2[2][0], a2, b0); ffma2(s2[2][1], a2, b1); ffma2(s2[2][2], a2, b2); ffma2(s2[2][3], a2, b3);
            ffma2(s2[2][4], a2, b4); ffma2(s2[2][5], a2, b5); ffma2(s2[2][6], a2, b6); ffma2(s2[2][7], a2, b7);
            ffma2(s2[3][0], a3, b0); ffma2(s2[3][1], a3, b1); ffma2(s2[3][2], a3, b2); ffma2(s2[3][3], a3, b3);
            ffma2(s2[3][4], a3, b4); ffma2(s2[3][5], a3, b5); ffma2(s2[3][6], a3, b6); ffma2(s2[3][7], a3, b7);
        }

        // ---- online softmax (values already in log2 domain) ----
        #pragma unroll
        for (int rp = 0; rp < 4; ++rp) {
            float pe[8], po[8];
            float fe, fo;
            {   // even row of pair (lo halves), r = 2*rp
                const int r = 2 * rp;
                float v0 = lo2(s2[rp][0]), v1 = lo2(s2[rp][1]), v2 = lo2(s2[rp][2]), v3 = lo2(s2[rp][3]);
                float v4 = lo2(s2[rp][4]), v5 = lo2(s2[rp][5]), v6 = lo2(s2[rp][6]), v7 = lo2(s2[rp][7]);
                float rmax = fmaxf(fmaxf(fmaxf(v0, v1), fmaxf(v2, v3)),
                                   fmaxf(fmaxf(v4, v5), fmaxf(v6, v7)));
                #pragma unroll
                for (int off = 8; off >= 1; off >>= 1)
                    rmax = fmaxf(rmax, __shfl_xor_sync(0xffffffffu, rmax, off));
                float mnew = fmaxf(m[r], rmax);
                fe = ex2f(m[r] - mnew);
                pe[0] = ex2f(v0 - mnew); pe[1] = ex2f(v1 - mnew); pe[2] = ex2f(v2 - mnew); pe[3] = ex2f(v3 - mnew);
                pe[4] = ex2f(v4 - mnew); pe[5] = ex2f(v5 - mnew); pe[6] = ex2f(v6 - mnew); pe[7] = ex2f(v7 - mnew);
                float rsum = ((pe[0] + pe[1]) + (pe[2] + pe[3])) + ((pe[4] + pe[5]) + (pe[6] + pe[7]));
                #pragma unroll
                for (int off = 8; off >= 1; off >>= 1)
                    rsum += __shfl_xor_sync(0xffffffffu, rsum, off);
                l[r] = l[r] * fe + rsum;
                m[r] = mnew;
            }
            {   // odd row of pair (hi halves), r = 2*rp+1
                const int r = 2 * rp + 1;
                float v0 = hi2(s2[rp][0]), v1 = hi2(s2[rp][1]), v2 = hi2(s2[rp][2]), v3 = hi2(s2[rp][3]);
                float v4 = hi2(s2[rp][4]), v5 = hi2(s2[rp][5]), v6 = hi2(s2[rp][6]), v7 = hi2(s2[rp][7]);
                float rmax = fmaxf(fmaxf(fmaxf(v0, v1), fmaxf(v2, v3)),
                                   fmaxf(fmaxf(v4, v5), fmaxf(v6, v7)));
                #pragma unroll
                for (int off = 8; off >= 1; off >>= 1)
                    rmax = fmaxf(rmax, __shfl_xor_sync(0xffffffffu, rmax, off));
                float mnew = fmaxf(m[r], rmax);
                fo = ex2f(m[r] - mnew);
                po[0] = ex2f(v0 - mnew); po[1] = ex2f(v1 - mnew); po[2] = ex2f(v2 - mnew); po[3] = ex2f(v3 - mnew);
                po[4] = ex2f(v4 - mnew); po[5] = ex2f(v5 - mnew); po[6] = ex2f(v6 - mnew); po[7] = ex2f(v7 - mnew);
                float rsum = ((po[0] + po[1]) + (po[2] + po[3])) + ((po[4] + po[5]) + (po[6] + po[7]));
                #pragma unroll
                for (int off = 8; off >= 1; off >>= 1)
                    rsum += __shfl_xor_sync(0xffffffffu, rsum, off);
                l[r] = l[r] * fo + rsum;
                m[r] = mnew;
            }
            u64 f2 = pack2(fe, fo);
            #pragma unroll
            for (int j = 0; j < 4; ++j) fmul2(acc[rp][j], f2);
            #pragma unroll
            for (int j = 0; j < 8; ++j) s2[rp][j] = pack2(pe[j], po[j]);
        }

        __syncthreads();   // all K^T reads done; safe to overwrite with P

        // ---- store P (row-pair packed, rotation swizzle: conflict-free) ----
        #pragma unroll
        for (int j = 0; j < 8; ++j) {
            int k = tx * 8 + j;
            u64* pb = Ps + k * 64;
            #pragma unroll
            for (int rp = 0; rp < 4; ++rp)
                pb[(ty * 4 + rp + tx) & 63] = s2[rp][j];
        }
        __syncthreads();

        // ---- GEMM2: acc += P @ V_tile ----
        const float* vp = Vs + tx * 4;
        #pragma unroll 2
        for (int k = 0; k < BN; ++k) {
            const u64* pb = Ps + k * 64;
            int cr = ty * 4 + (k >> 3);
            u64 a0 = pb[(cr + 0) & 63];
            u64 a1 = pb[(cr + 1) & 63];
            u64 a2 = pb[(cr + 2) & 63];
            u64 a3 = pb[(cr + 3) & 63];
            float4 Bv = *(const float4*)(vp + k * VS_STRIDE);
            u64 b0 = splat2(Bv.x), b1 = splat2(Bv.y), b2 = splat2(Bv.z), b3 = splat2(Bv.w);
            ffma2(acc[0][0], a0, b0); ffma2(acc[0][1], a0, b1); ffma2(acc[0][2], a0, b2); ffma2(acc[0][3], a0, b3);
            ffma2(acc[1][0], a1, b0); ffma2(acc[1][1], a1, b1); ffma2(acc[1][2], a1, b2); ffma2(acc[1][3], a1, b3);
            ffma2(acc[2][0], a2, b0); ffma2(acc[2][1], a2, b1); ffma2(acc[2][2], a2, b2); ffma2(acc[2][3], a2, b3);
            ffma2(acc[3][0], a3, b0); ffma2(acc[3][1], a3, b1); ffma2(acc[3][2], a3, b2); ffma2(acc[3][3], a3, b3);
        }
    }

    // ---- epilogue: normalize and store ----
    #pragma unroll
    for (int rp = 0; rp < 4; ++rp) {
        u64 inv2 = pack2(1.0f / l[2 * rp], 1.0f / l[2 * rp + 1]);
        #pragma unroll
        for (int j = 0; j < 4; ++j) fmul2(acc[rp][j], inv2);
        int g0 = qbase + ty * 8 + 2 * rp;
        float4 oe, oo;
        oe.x = lo2(acc[rp][0]); oe.y = lo2(acc[rp][1]); oe.z = lo2(acc[rp][2]); oe.w = lo2(acc[rp][3]);
        oo.x = hi2(acc[rp][0]); oo.y = hi2(acc[rp][1]); oo.z = hi2(acc[rp][2]); oo.w = hi2(acc[rp][3]);
        *(float4*)&O[base + (size_t)g0 * DH + tx * 4] = oe;
        *(float4*)&O[base + (size_t)(g0 + 1) * DH + tx * 4] = oo;
    }
}

extern "C" void kernel_launch(void* const* d_in, const int* in_sizes, int n_in,
                              void* d_out, int out_size)
{
    const float* Q = (const float*)d_in[0];
    const float* K = (const float*)d_in[1];
    const float* V = (const float*)d_in[2];
    float* O = (float*)d_out;

    const int S = 2048;   // B=4, H=16, S=2048, D=64 fixed by the problem
    const int BH = 64;

    cudaFuncSetAttribute(attn_f32x2_kernel,
                         cudaFuncAttributeMaxDynamicSharedMemorySize, SMEM_BYTES);

    dim3 grid(S / BM, BH);
    attn_f32x2_kernel<<<grid, NT, SMEM_BYTES>>>(Q, K, V, O, S);
}

// round 7
// speedup vs baseline: 4.0997x; 3.2697x over previous
#include <cuda_runtime.h>

// Scaled dot-product attention, B=4 H=16 S=2048 D=64, fp32 in/out.
// Flash-attention on tensor cores: mma.sync.m16n8k8 tf32 (round-to-nearest cvt).
// CTA: 128 queries x 128 keys per iteration, 8 warps; warp = 16 rows x 128 cols.

#define DH 64
#define BM 128
#define BN 128
#define NT 256

#define KS_STRIDE 68   /* words per K row: gid*4+tig bank pattern, conflict-free */
#define VS_STRIDE 72   /* words per V row: tig*8+gid bank pattern, conflict-free */
#define KS_BYTES (BN * KS_STRIDE * 4)            /* 34816 */
#define VS_BYTES (BN * VS_STRIDE * 4)            /* 36864 */
#define SMEM_BYTES (KS_BYTES + VS_BYTES)         /* 71680 */

__device__ __forceinline__ unsigned tf32b(float x) {
    unsigned u;
    asm("cvt.rna.tf32.f32 %0, %1;" : "=r"(u) : "f"(x));
    return u;
}
__device__ __forceinline__ float ex2f(float x) {
    float r; asm("ex2.approx.f32 %0, %1;" : "=f"(r) : "f"(x)); return r;
}
__device__ __forceinline__ void mma_tf32(float c[4],
                                         const unsigned a[4],
                                         unsigned b0, unsigned b1) {
    asm("mma.sync.aligned.m16n8k8.row.col.f32.tf32.tf32.f32 "
        "{%0,%1,%2,%3}, {%4,%5,%6,%7}, {%8,%9}, {%0,%1,%2,%3};"
        : "+f"(c[0]), "+f"(c[1]), "+f"(c[2]), "+f"(c[3])
        : "r"(a[0]), "r"(a[1]), "r"(a[2]), "r"(a[3]), "r"(b0), "r"(b1));
}

__global__ void __launch_bounds__(NT, 1) attn_tf32_kernel(
    const float* __restrict__ Q,
    const float* __restrict__ K,
    const float* __restrict__ V,
    float* __restrict__ O,
    int S)
{
    extern __shared__ char smem[];
    unsigned* Ks = (unsigned*)smem;               // tf32 bits, K[row][d], stride 68
    unsigned* Vs = (unsigned*)(smem + KS_BYTES);  // tf32 bits, V[row][d], stride 72

    const int tid  = threadIdx.x;
    const int lane = tid & 31;
    const int warp = tid >> 5;
    const int gid  = lane >> 2;   // group id (row within fragment)
    const int tig  = lane & 3;    // thread in group (col within fragment)

    const size_t base = (size_t)blockIdx.y * ((size_t)S * DH);
    const int qbase = blockIdx.x * BM;

    // ---- stage Q (scaled to log2 domain, tf32) into Ks, grab fragments ----
    const float SC = 0.125f * 1.4426950408889634f;
    #pragma unroll
    for (int it = 0; it < 8; ++it) {
        int idx = tid + it * NT;
        int row = idx >> 4;
        int d4 = (idx & 15) << 2;
        float4 v = *(const float4*)&Q[base + (size_t)(qbase + row) * DH + d4];
        uint4 u;
        u.x = tf32b(v.x * SC); u.y = tf32b(v.y * SC);
        u.z = tf32b(v.z * SC); u.w = tf32b(v.w * SC);
        *(uint4*)&Ks[row * KS_STRIDE + d4] = u;
    }
    __syncthreads();

    unsigned qa[8][4];                 // Q fragments: 8 d-chunks of m16k8
    {
        const int r0 = warp * 16 + gid;
        #pragma unroll
        for (int kc = 0; kc < 8; ++kc) {
            qa[kc][0] = Ks[(r0    ) * KS_STRIDE + kc * 8 + tig];
            qa[kc][1] = Ks[(r0 + 8) * KS_STRIDE + kc * 8 + tig];
            qa[kc][2] = Ks[(r0    ) * KS_STRIDE + kc * 8 + tig + 4];
            qa[kc][3] = Ks[(r0 + 8) * KS_STRIDE + kc * 8 + tig + 4];
        }
    }

    float o[8][4];                     // O accum: 8 n-tiles of 16x8
    #pragma unroll
    for (int nt = 0; nt < 8; ++nt)
        #pragma unroll
        for (int j = 0; j < 4; ++j) o[nt][j] = 0.0f;
    float m0 = -1e30f, m1 = -1e30f, l0 = 0.0f, l1 = 0.0f;

    const int srcA = (lane & 28) | (tig >> 1);
    const int srcB = srcA + 2;
    const bool odd = (tig & 1) != 0;

    const int nkt = S / BN;
    for (int kt = 0; kt < nkt; ++kt) {
        const int kb = kt * BN;
        __syncthreads();   // Q-frag reads / prev-iter smem reads complete

        // ---- stage K and V tiles (converted to tf32 bits) ----
        #pragma unroll
        for (int it = 0; it < 8; ++it) {
            int idx = tid + it * NT;
            int row = idx >> 4;
            int d4 = (idx & 15) << 2;
            float4 v = *(const float4*)&K[base + (size_t)(kb + row) * DH + d4];
            uint4 u;
            u.x = tf32b(v.x); u.y = tf32b(v.y); u.z = tf32b(v.z); u.w = tf32b(v.w);
            *(uint4*)&Ks[row * KS_STRIDE + d4] = u;
        }
        #pragma unroll
        for (int it = 0; it < 8; ++it) {
            int idx = tid + it * NT;
            int row = idx >> 4;
            int d4 = (idx & 15) << 2;
            float4 v = *(const float4*)&V[base + (size_t)(kb + row) * DH + d4];
            uint4 u;
            u.x = tf32b(v.x); u.y = tf32b(v.y); u.z = tf32b(v.z); u.w = tf32b(v.w);
            *(uint4*)&Vs[row * VS_STRIDE + d4] = u;
        }
        __syncthreads();

        // ---- GEMM1: S = Q @ K^T  (16 n-tiles of 16x8, k = d in 8 chunks) ----
        float c[16][4];
        #pragma unroll
        for (int nt = 0; nt < 16; ++nt)
            #pragma unroll
            for (int j = 0; j < 4; ++j) c[nt][j] = 0.0f;

        #pragma unroll
        for (int kc = 0; kc < 8; ++kc) {
            #pragma unroll
            for (int nt = 0; nt < 16; ++nt) {
                unsigned b0 = Ks[(nt * 8 + gid) * KS_STRIDE + kc * 8 + tig];
                unsigned b1 = Ks[(nt * 8 + gid) * KS_STRIDE + kc * 8 + tig + 4];
                mma_tf32(c[nt], qa[kc], b0, b1);
            }
        }

        // ---- online softmax (log2 domain). Thread owns rows gid, gid+8. ----
        float mx0 = -1e30f, mx1 = -1e30f;
        #pragma unroll
        for (int nt = 0; nt < 16; ++nt) {
            mx0 = fmaxf(mx0, fmaxf(c[nt][0], c[nt][1]));
            mx1 = fmaxf(mx1, fmaxf(c[nt][2], c[nt][3]));
        }
        #pragma unroll
        for (int off = 1; off <= 2; off <<= 1) {
            mx0 = fmaxf(mx0, __shfl_xor_sync(0xffffffffu, mx0, off));
            mx1 = fmaxf(mx1, __shfl_xor_sync(0xffffffffu, mx1, off));
        }
        float mn0 = fmaxf(m0, mx0), mn1 = fmaxf(m1, mx1);
        float f0 = ex2f(m0 - mn0), f1 = ex2f(m1 - mn1);
        m0 = mn0; m1 = mn1;

        float s0 = 0.0f, s1 = 0.0f;
        #pragma unroll
        for (int nt = 0; nt < 16; ++nt) {
            c[nt][0] = ex2f(c[nt][0] - mn0);
            c[nt][1] = ex2f(c[nt][1] - mn0);
            c[nt][2] = ex2f(c[nt][2] - mn1);
            c[nt][3] = ex2f(c[nt][3] - mn1);
            s0 += c[nt][0] + c[nt][1];
            s1 += c[nt][2] + c[nt][3];
        }
        #pragma unroll
        for (int off = 1; off <= 2; off <<= 1) {
            s0 += __shfl_xor_sync(0xffffffffu, s0, off);
            s1 += __shfl_xor_sync(0xffffffffu, s1, off);
        }
        l0 = l0 * f0 + s0;
        l1 = l1 * f1 + s1;

        #pragma unroll
        for (int nt = 0; nt < 8; ++nt) {
            o[nt][0] *= f0; o[nt][1] *= f0;
            o[nt][2] *= f1; o[nt][3] *= f1;
        }

        // ---- P: C-frag -> A-frag (quad shuffles), fused with GEMM2 ----
        #pragma unroll
        for (int kc = 0; kc < 16; ++kc) {
            float x0 = __shfl_sync(0xffffffffu, c[kc][0], srcA);
            float x1 = __shfl_sync(0xffffffffu, c[kc][1], srcA);
            float y0 = __shfl_sync(0xffffffffu, c[kc][0], srcB);
            float y1 = __shfl_sync(0xffffffffu, c[kc][1], srcB);
            float z0 = __shfl_sync(0xffffffffu, c[kc][2], srcA);
            float z1 = __shfl_sync(0xffffffffu, c[kc][3], srcA);
            float w0 = __shfl_sync(0xffffffffu, c[kc][2], srcB);
            float w1 = __shfl_sync(0xffffffffu, c[kc][3], srcB);
            unsigned pa[4];
            pa[0] = tf32b(odd ? x1 : x0);
            pa[2] = tf32b(odd ? y1 : y0);
            pa[1] = tf32b(odd ? z1 : z0);
            pa[3] = tf32b(odd ? w1 : w0);
            #pragma unroll
            for (int nt2 = 0; nt2 < 8; ++nt2) {
                unsigned b0 = Vs[(kc * 8 + tig    ) * VS_STRIDE + nt2 * 8 + gid];
                unsigned b1 = Vs[(kc * 8 + tig + 4) * VS_STRIDE + nt2 * 8 + gid];
                mma_tf32(o[nt2], pa, b0, b1);
            }
        }
    }

    // ---- epilogue ----
    const float inv0 = 1.0f / l0, inv1 = 1.0f / l1;
    const int r0 = qbase + warp * 16 + gid;
    const int r1 = r0 + 8;
    #pragma unroll
    for (int nt2 = 0; nt2 < 8; ++nt2) {
        float2 e0, e1;
        e0.x = o[nt2][0] * inv0; e0.y = o[nt2][1] * inv0;
        e1.x = o[nt2][2] * inv1; e1.y = o[nt2][3] * inv1;
        *(float2*)&O[base + (size_t)r0 * DH + nt2 * 8 + 2 * tig] = e0;
        *(float2*)&O[base + (size_t)r1 * DH + nt2 * 8 + 2 * tig] = e1;
    }
}

extern "C" void kernel_launch(void* const* d_in, const int* in_sizes, int n_in,
                              void* d_out, int out_size)
{
    const float* Q = (const float*)d_in[0];
    const float* K = (const float*)d_in[1];
    const float* V = (const float*)d_in[2];
    float* O = (float*)d_out;

    const int S = 2048;   // B=4, H=16, S=2048, D=64 fixed by the problem

    cudaFuncSetAttribute(attn_tf32_kernel,
                         cudaFuncAttributeMaxDynamicSharedMemorySize, SMEM_BYTES);

    dim3 grid(S / BM, 64);
    attn_tf32_kernel<<<grid, NT, SMEM_BYTES>>>(Q, K, V, O, S);
}